// round 12
// baseline (speedup 1.0000x reference)
#include <cuda_runtime.h>
#include <cuda_fp16.h>
#include <cstdint>

// MASLoRALinear, fp16 HMMA.
//   k_prep:   wbh=half(W_base), ah=half(Acat), bch=half(Bcat)   (small, ~3us)
//   k_lora_h: loader reads fp32 x, converts in-reg, STS fp16 + STG g_xh;
//             Hh[m,n] = half( SCALE * w[b(m), n>>4] * (x @ Acat^T)[m,n] )
//   k_main:   out[m,o] = bb[o] + (xh @ wbh^T)[m,o] + (Hh @ bch^T)[m,o]  (R11 verbatim)

namespace {
constexpr int Tt = 1500, Cc = 1024, Oo = 1024, Ee = 8, Rr = 16;
constexpr int Mm = 16 * Tt;          // 24000
constexpr int ER = Ee * Rr;          // 128
constexpr float SCALE = 32.0f / 16.0f;
constexpr int STAGE = 16384;         // A 8KB + B 8KB (fp16, BK=32)
constexpr int NSTAGE = 3;            // k_main pipeline depth
constexpr int DYN_SMEM = NSTAGE * STAGE;
constexpr int DYN_SMEM_L = 2 * STAGE;  // k_lora_h: sync double buffer
}

__device__ __half g_xh[(size_t)Mm * Cc];     // 24000x1024
__device__ __half g_wbh[(size_t)Oo * Cc];    // 1024x1024
__device__ __half g_ah[(size_t)ER * Cc];     // 128x1024 (Acat)
__device__ __half g_bch[(size_t)Oo * ER];    // 1024x128 (Bcat)
__device__ __half g_Hh[(size_t)Mm * ER];     // 24000x128

// ---------------------------------------------------------------------------
__device__ __forceinline__ uint32_t smem_u32(const void* p) {
    uint32_t a;
    asm("{ .reg .u64 t; cvta.to.shared.u64 t, %1; cvt.u32.u64 %0, t; }" : "=r"(a) : "l"(p));
    return a;
}

#define CP16(s, g) \
    asm volatile("cp.async.cg.shared.global [%0], [%1], 16;" :: "r"(s), "l"(g))
#define CP_COMMIT() asm volatile("cp.async.commit_group;" ::: "memory")
#define CP_WAIT1() asm volatile("cp.async.wait_group 1;" ::: "memory")
#define CP_WAIT0() asm volatile("cp.async.wait_group 0;" ::: "memory")

#define LDSM_X4(r0, r1, r2, r3, a) \
    asm volatile("ldmatrix.sync.aligned.m8n8.x4.shared.b16 {%0,%1,%2,%3}, [%4];" \
                 : "=r"(r0), "=r"(r1), "=r"(r2), "=r"(r3) : "r"(a))

#define MMA_F16(d, a, b) \
    asm volatile("mma.sync.aligned.m16n8k16.row.col.f32.f16.f16.f32 " \
                 "{%0,%1,%2,%3},{%4,%5,%6,%7},{%8,%9},{%0,%1,%2,%3};" \
                 : "+f"((d)[0]), "+f"((d)[1]), "+f"((d)[2]), "+f"((d)[3]) \
                 : "r"((a)[0]), "r"((a)[1]), "r"((a)[2]), "r"((a)[3]), \
                   "r"((b)[0]), "r"((b)[1]))

// swizzled byte offset within an 8KB tile: 64B rows, 4x16B cols, xor swizzle
__device__ __forceinline__ uint32_t swz(int r, int c) {
    return (uint32_t)(r * 64 + ((c ^ ((r >> 1) & 3)) << 4));
}

// one BK=32 chunk: 2 k-steps x (4 m x 4 n) MMAs
__device__ __forceinline__ void compute_chunk(float (&acc)[4][4][4],
                                              uint32_t base,
                                              const uint32_t* offA,
                                              const uint32_t* offB) {
    const uint32_t aB = base, bB = base + 8192u;
#pragma unroll
    for (int ks = 0; ks < 2; ks++) {
        uint32_t aF[4][4], bF[4][2];
#pragma unroll
        for (int mi = 0; mi < 4; mi++)
            LDSM_X4(aF[mi][0], aF[mi][1], aF[mi][2], aF[mi][3], aB + offA[mi * 2 + ks]);
#pragma unroll
        for (int j = 0; j < 2; j++) {
            uint32_t t0, t1, t2, t3;
            LDSM_X4(t0, t1, t2, t3, bB + offB[j * 2 + ks]);
            bF[2 * j][0] = t0; bF[2 * j][1] = t1;
            bF[2 * j + 1][0] = t2; bF[2 * j + 1][1] = t3;
        }
#pragma unroll
        for (int mi = 0; mi < 4; mi++)
#pragma unroll
            for (int ni = 0; ni < 4; ni++)
                MMA_F16(acc[mi][ni], aF[mi], bF[ni]);
    }
}

__device__ __forceinline__ void make_offsets(int lane, int wm, int wn,
                                             uint32_t* offA, uint32_t* offB) {
    int g = lane >> 3, wr = lane & 7;
#pragma unroll
    for (int mi = 0; mi < 4; mi++)
#pragma unroll
        for (int ks = 0; ks < 2; ks++) {
            int r = wm * 64 + mi * 16 + (g & 1) * 8 + wr;
            offA[mi * 2 + ks] = swz(r, ks * 2 + (g >> 1));
        }
#pragma unroll
    for (int j = 0; j < 2; j++)
#pragma unroll
        for (int ks = 0; ks < 2; ks++) {
            int n = wn * 32 + j * 16 + (g >> 1) * 8 + wr;
            offB[j * 2 + ks] = swz(n, ks * 2 + (g & 1));
        }
}

// ---------------------------------------------------------------------------
// small prep: Wb->wbh, Acat->ah, Bcat->bch  (grid-stride, ~6.75MB)
// ---------------------------------------------------------------------------
__global__ void k_prep(const float* __restrict__ Wb, const float* __restrict__ As,
                       const float* __restrict__ Bs) {
    const int stride = gridDim.x * blockDim.x;
    const int gtid = blockIdx.x * blockDim.x + threadIdx.x;
    for (int i = gtid; i < Oo * Cc / 4; i += stride) {          // Wb
        float4 v = *(const float4*)(Wb + (size_t)i * 4);
        __half2 h0 = __float22half2_rn(make_float2(v.x, v.y));
        __half2 h1 = __float22half2_rn(make_float2(v.z, v.w));
        *(uint2*)(g_wbh + (size_t)i * 4) = make_uint2(*(uint32_t*)&h0, *(uint32_t*)&h1);
    }
    for (int i = gtid; i < ER * Cc / 4; i += stride) {          // Acat
        float4 v = *(const float4*)(As + (size_t)i * 4);
        __half2 h0 = __float22half2_rn(make_float2(v.x, v.y));
        __half2 h1 = __float22half2_rn(make_float2(v.z, v.w));
        *(uint2*)(g_ah + (size_t)i * 4) = make_uint2(*(uint32_t*)&h0, *(uint32_t*)&h1);
    }
    for (int idx = gtid; idx < Oo * ER; idx += stride) {        // Bcat transpose
        int o = idx >> 7, n = idx & 127;
        g_bch[idx] = __float2half(Bs[(((size_t)(n >> 4)) * Oo + o) * Rr + (n & 15)]);
    }
}

// ---------------------------------------------------------------------------
// Kernel 1: fused x-convert + Hh GEMM.  128x128 tile, 32 chunks of BK=32.
// Sync double-buffer (R4/R6-proven loop). Loader also streams fp16 x to g_xh.
// ---------------------------------------------------------------------------
__global__ __launch_bounds__(256, 2)
void k_lora_h(const float* __restrict__ x, const float* __restrict__ w) {
    extern __shared__ char dsm[];
    const uint32_t sb = smem_u32(dsm);
    const int tid = threadIdx.x;
    const int lane = tid & 31, wid = tid >> 5;
    const int wm = wid >> 2, wn = wid & 3;
    const int bm = blockIdx.x * 128;

    // x loader: row = tid>>1 (0..127), half = tid&1 (16 fp32 cols each)
    const int row = tid >> 1, half = tid & 1;
    const int mrow = min(bm + row, Mm - 1);
    const bool wr_ok = (bm + row) < Mm;
    const float* xrow = x + (size_t)mrow * Cc + half * 16;
    __half* xhrow = g_xh + (size_t)mrow * Cc + half * 16;
    const uint32_t xo0 = swz(row, half * 2), xo1 = swz(row, half * 2 + 1);

    // Acat loader: rows ar, ar+64; 16B slot ac
    const int ar = tid >> 2, ac = tid & 3;
    const __half* arow0 = g_ah + (size_t)ar * Cc + ac * 8;
    const __half* arow1 = g_ah + (size_t)(ar + 64) * Cc + ac * 8;
    const uint32_t ao0 = swz(ar, ac), ao1 = swz(ar + 64, ac);

    uint32_t offA[8], offB[4];
    make_offsets(lane, wm, wn, offA, offB);

    float acc[4][4][4];
#pragma unroll
    for (int a = 0; a < 4; a++)
#pragma unroll
        for (int b = 0; b < 4; b++)
#pragma unroll
            for (int c = 0; c < 4; c++) acc[a][b][c] = 0.0f;

    uint4 xq[2], aq[2];
    auto ldg_cvt = [&](int ch) {
        const float* p = xrow + ch * 32;
        float4 v0 = *(const float4*)(p);
        float4 v1 = *(const float4*)(p + 4);
        float4 v2 = *(const float4*)(p + 8);
        float4 v3 = *(const float4*)(p + 12);
        __half2 h;
        h = __float22half2_rn(make_float2(v0.x, v0.y)); xq[0].x = *(uint32_t*)&h;
        h = __float22half2_rn(make_float2(v0.z, v0.w)); xq[0].y = *(uint32_t*)&h;
        h = __float22half2_rn(make_float2(v1.x, v1.y)); xq[0].z = *(uint32_t*)&h;
        h = __float22half2_rn(make_float2(v1.z, v1.w)); xq[0].w = *(uint32_t*)&h;
        h = __float22half2_rn(make_float2(v2.x, v2.y)); xq[1].x = *(uint32_t*)&h;
        h = __float22half2_rn(make_float2(v2.z, v2.w)); xq[1].y = *(uint32_t*)&h;
        h = __float22half2_rn(make_float2(v3.x, v3.y)); xq[1].z = *(uint32_t*)&h;
        h = __float22half2_rn(make_float2(v3.z, v3.w)); xq[1].w = *(uint32_t*)&h;
        aq[0] = *(const uint4*)(arow0 + ch * 32);
        aq[1] = *(const uint4*)(arow1 + ch * 32);
        // stream converted x to g_xh for k_main (overlaps with compute)
        if (wr_ok) {
            *(uint4*)(xhrow + ch * 32) = xq[0];
            *(uint4*)(xhrow + ch * 32 + 8) = xq[1];
        }
    };
    auto sts = [&](char* base) {
        *(uint4*)(base + xo0) = xq[0];
        *(uint4*)(base + xo1) = xq[1];
        *(uint4*)(base + 8192 + ao0) = aq[0];
        *(uint4*)(base + 8192 + ao1) = aq[1];
    };

    const int NCH = 32;
    ldg_cvt(0);
    sts(dsm);
    __syncthreads();

#pragma unroll 1
    for (int ch = 0; ch < NCH; ch++) {
        const int s = ch & 1;
        if (ch + 1 < NCH) ldg_cvt(ch + 1);
        compute_chunk(acc, sb + (uint32_t)s * STAGE, offA, offB);
        __syncthreads();
        if (ch + 1 < NCH) {
            sts(dsm + (s ^ 1) * STAGE);
            __syncthreads();
        }
    }

    // epilogue: scale and store fp16 H
#pragma unroll
    for (int mi = 0; mi < 4; mi++) {
#pragma unroll
        for (int ni = 0; ni < 4; ni++) {
            int n = wn * 32 + ni * 8 + 2 * (lane & 3);
            int e = n >> 4;
            int m0 = bm + wm * 64 + mi * 16 + (lane >> 2);
            if (m0 < Mm) {
                float sw = SCALE * __ldg(&w[(m0 / Tt) * Ee + e]);
                __half2 h = __float22half2_rn(make_float2(acc[mi][ni][0] * sw, acc[mi][ni][1] * sw));
                *(__half2*)(&g_Hh[(size_t)m0 * ER + n]) = h;
            }
            int m1 = m0 + 8;
            if (m1 < Mm) {
                float sw = SCALE * __ldg(&w[(m1 / Tt) * Ee + e]);
                __half2 h = __float22half2_rn(make_float2(acc[mi][ni][2] * sw, acc[mi][ni][3] * sw));
                *(__half2*)(&g_Hh[(size_t)m1 * ER + n]) = h;
            }
        }
    }
}

// ---------------------------------------------------------------------------
// Kernel 2: out = xh @ wbh^T + Hh @ bch^T + bb; 36 chunks  (R11 verbatim)
// ---------------------------------------------------------------------------
__global__ __launch_bounds__(256, 2)
void k_main(const float* __restrict__ bb, float* __restrict__ out) {
    extern __shared__ char dsm[];
    const uint32_t sb = smem_u32(dsm);
    const int tid = threadIdx.x;
    const int lane = tid & 31, wid = tid >> 5;
    const int wm = wid >> 2, wn = wid & 3;
    const int bn = blockIdx.x * 128;
    const int bm = blockIdx.y * 128;

    const int r0 = tid >> 2, cc4 = tid & 3;
    const size_t mA0 = (size_t)min(bm + r0, Mm - 1);
    const size_t mA1 = (size_t)min(bm + r0 + 64, Mm - 1);
    const __half* xa0 = g_xh + mA0 * Cc + cc4 * 8;
    const __half* xa1 = g_xh + mA1 * Cc + cc4 * 8;
    const __half* wb0 = g_wbh + (size_t)(bn + r0) * Cc + cc4 * 8;
    const __half* wb1 = g_wbh + (size_t)(bn + r0 + 64) * Cc + cc4 * 8;
    const __half* ha0 = g_Hh + mA0 * ER + cc4 * 8;
    const __half* ha1 = g_Hh + mA1 * ER + cc4 * 8;
    const __half* bc0 = g_bch + (size_t)(bn + r0) * ER + cc4 * 8;
    const __half* bc1 = g_bch + (size_t)(bn + r0 + 64) * ER + cc4 * 8;
    const uint32_t o0 = swz(r0, cc4), o1 = swz(r0 + 64, cc4);

    uint32_t offA[8], offB[4];
    make_offsets(lane, wm, wn, offA, offB);

    float acc[4][4][4];
#pragma unroll
    for (int a = 0; a < 4; a++)
#pragma unroll
        for (int b = 0; b < 4; b++)
#pragma unroll
            for (int c = 0; c < 4; c++) acc[a][b][c] = 0.0f;

    const int NCH = 36;

    auto issue = [&](int ch) {
        uint32_t st = sb + (uint32_t)(ch % NSTAGE) * STAGE;
        const __half *a0, *a1, *b0, *b1;
        if (ch < 32) {
            a0 = xa0 + ch * 32; a1 = xa1 + ch * 32;
            b0 = wb0 + ch * 32; b1 = wb1 + ch * 32;
        } else {
            int c2 = ch - 32;
            a0 = ha0 + c2 * 32; a1 = ha1 + c2 * 32;
            b0 = bc0 + c2 * 32; b1 = bc1 + c2 * 32;
        }
        CP16(st + o0, a0); CP16(st + o1, a1);
        CP16(st + 8192u + o0, b0); CP16(st + 8192u + o1, b1);
        CP_COMMIT();
    };

    issue(0);
    issue(1);

#pragma unroll 1
    for (int ch = 0; ch < NCH; ch++) {
        if (ch + 1 < NCH) CP_WAIT1(); else CP_WAIT0();
        __syncthreads();
        if (ch + 2 < NCH) issue(ch + 2);
        compute_chunk(acc, sb + (uint32_t)(ch % NSTAGE) * STAGE, offA, offB);
    }

    // epilogue: add bias, store fp32
#pragma unroll
    for (int mi = 0; mi < 4; mi++) {
#pragma unroll
        for (int ni = 0; ni < 4; ni++) {
            int col = bn + wn * 32 + ni * 8 + 2 * (lane & 3);
            float2 bias = *(const float2*)(bb + col);
            int m0 = bm + wm * 64 + mi * 16 + (lane >> 2);
            if (m0 < Mm) {
                float2 o = make_float2(acc[mi][ni][0] + bias.x, acc[mi][ni][1] + bias.y);
                *(float2*)(out + (size_t)m0 * Oo + col) = o;
            }
            int m1 = m0 + 8;
            if (m1 < Mm) {
                float2 o = make_float2(acc[mi][ni][2] + bias.x, acc[mi][ni][3] + bias.y);
                *(float2*)(out + (size_t)m1 * Oo + col) = o;
            }
        }
    }
}

// ---------------------------------------------------------------------------
extern "C" void kernel_launch(void* const* d_in, const int* in_sizes, int n_in,
                              void* d_out, int out_size) {
    const float* x  = (const float*)d_in[0];   // (16,1500,1024)
    const float* w  = (const float*)d_in[1];   // (16,8)
    const float* Wb = (const float*)d_in[2];   // (1024,1024)
    const float* bb = (const float*)d_in[3];   // (1024,)
    const float* As = (const float*)d_in[4];   // (8,16,1024) = Acat (128,1024)
    const float* Bs = (const float*)d_in[5];   // (8,1024,16)
    float* out = (float*)d_out;

    cudaFuncSetAttribute(k_lora_h, cudaFuncAttributeMaxDynamicSharedMemorySize, DYN_SMEM_L);
    cudaFuncSetAttribute(k_main, cudaFuncAttributeMaxDynamicSharedMemorySize, DYN_SMEM);

    // small prep: Wb + Acat + Bcat only (~3us)
    k_prep<<<592, 256>>>(Wb, As, Bs);

    // fused x-convert + lora GEMM
    const int grid_m = (Mm + 127) / 128;  // 188
    k_lora_h<<<grid_m, 256, DYN_SMEM_L>>>(x, w);

    dim3 g2(Oo / 128, grid_m);            // (8, 188)
    k_main<<<g2, 256, DYN_SMEM>>>(bb, out);
}